// round 15
// baseline (speedup 1.0000x reference)
#include <cuda_runtime.h>
#include <cuda_fp16.h>
#include <mma.h>
#include <math.h>

using namespace nvcuda;

#define Bn 4
#define Ln 2048
#define Dn 768
#define Hn 12
#define Kn 9
#define IPGn 64
#define PADn 4

__device__ __half g_v16[Bn * Ln * Dn];     // 12.6 MB fp16 v (+bias folded)
__device__ float g_w[Bn * Ln * Hn * Kn];   // 3.5 MB softmax weights
__device__ __half g_ptw16[Dn * Dn];        // 1.2 MB fp16 pt_w

struct SideStream {
    cudaStream_t s2;
    cudaEvent_t e_fork, e_half, e_join;
    SideStream() {
        cudaStreamCreateWithFlags(&s2, cudaStreamNonBlocking);
        cudaEventCreateWithFlags(&e_fork, cudaEventDisableTiming);
        cudaEventCreateWithFlags(&e_half, cudaEventDisableTiming);
        cudaEventCreateWithFlags(&e_join, cudaEventDisableTiming);
    }
};
static SideStream g_ss;

__device__ __forceinline__ void cp_async16(void* smem, const void* gmem) {
    unsigned s = (unsigned)__cvta_generic_to_shared(smem);
    asm volatile("cp.async.cg.shared.global [%0], [%1], 16;\n" :: "r"(s), "l"(gmem));
}
__device__ __forceinline__ void cp_commit() {
    asm volatile("cp.async.commit_group;\n" ::);
}
template <int N>
__device__ __forceinline__ void cp_wait() {
    asm volatile("cp.async.wait_group %0;\n" :: "n"(N));
}

// ---------------------------------------------------------------------------
// fp32 -> fp16 conversion (pt_w only; tiny)
// ---------------------------------------------------------------------------
__global__ __launch_bounds__(256) void cvt_fp16(
    const float4* __restrict__ in, __half* __restrict__ out, int n4)
{
    int idx = blockIdx.x * 256 + threadIdx.x;
    if (idx < n4) {
        float4 f = in[idx];
        *reinterpret_cast<__half2*>(out + (size_t)idx * 4) =
            __floats2half2_rn(f.x, f.y);
        *reinterpret_cast<__half2*>(out + (size_t)idx * 4 + 2) =
            __floats2half2_rn(f.z, f.w);
    }
}

// ---------------------------------------------------------------------------
// Kernel 1: v16 = half(query @ ptw16.T + pt_b)
// fp16 wmma m16n16k16, fp32 accum. Block 128x128, 8 warps (2m x 4n) of 64x32.
// Launched in an ASYMMETRIC split: 288 CTAs (~1 full wave) then 96 CTAs
// (the tail wave) so the gather can overlap the underfilled tail.
// ---------------------------------------------------------------------------
#define GBM 128
#define GBN 128
#define GBK2 32
#define GLDH 40
#define SLD 20   // staging ldm: multiple of 4 (wmma float frag requirement)

__device__ __forceinline__ void lda_f32(
    const float* __restrict__ A, float4* r, int m0, int k0, int tid)
{
#pragma unroll
    for (int v = 0; v < 4; v++) {
        int idx = tid + v * 256;
        int row = idx >> 3, c4 = idx & 7;
        r[v] = *reinterpret_cast<const float4*>(
            &A[(size_t)(m0 + row) * Dn + k0 + c4 * 4]);
    }
}
__device__ __forceinline__ void sta_f16(__half* As, const float4* r, int tid)
{
#pragma unroll
    for (int v = 0; v < 4; v++) {
        int idx = tid + v * 256;
        int row = idx >> 3, c4 = idx & 7;
        __half2* p = reinterpret_cast<__half2*>(&As[row * GLDH + c4 * 4]);
        p[0] = __floats2half2_rn(r[v].x, r[v].y);
        p[1] = __floats2half2_rn(r[v].z, r[v].w);
    }
}
__device__ __forceinline__ void ldb_cp(
    const __half* __restrict__ W, __half* Bs, int n0, int k0, int tid)
{
#pragma unroll
    for (int v = 0; v < 2; v++) {
        int idx = tid + v * 256;
        int r = idx >> 2, c = idx & 3;
        cp_async16(&Bs[r * GLDH + c * 8], &W[(size_t)(n0 + r) * Dn + k0 + c * 8]);
    }
}

__global__ __launch_bounds__(256) void gemm_h2(
    const float* __restrict__ A, const __half* __restrict__ W,
    const float* __restrict__ pt_b, int mblk_base)
{
    __shared__ __align__(16) __half As[2][GBM * GLDH];
    __shared__ __align__(16) __half Bs[2][GBN * GLDH];
    __shared__ __align__(16) float stg[8][16 * SLD];
    __shared__ float pbs[GBN];

    const int tid = threadIdx.x;
    const int m0 = (mblk_base + blockIdx.y) * GBM;
    const int n0 = blockIdx.x * GBN;
    const int warp = tid >> 5;
    const int lane = tid & 31;
    const int wm = warp & 1;
    const int wn = warp >> 1;

    if (tid < GBN) pbs[tid] = pt_b[n0 + tid];

    wmma::fragment<wmma::accumulator, 16, 16, 16, float> cf[4][2];
#pragma unroll
    for (int mi = 0; mi < 4; mi++)
#pragma unroll
        for (int ni = 0; ni < 2; ni++)
            wmma::fill_fragment(cf[mi][ni], 0.0f);

    float4 areg[4];
    lda_f32(A, areg, m0, 0, tid);
    ldb_cp(W, Bs[0], n0, 0, tid);
    cp_commit();
    sta_f16(As[0], areg, tid);

    const int NKT = Dn / GBK2;  // 24
    for (int kt = 0; kt < NKT; kt++) {
        const int cur = kt & 1;
        if (kt + 1 < NKT) {
            lda_f32(A, areg, m0, (kt + 1) * GBK2, tid);
            ldb_cp(W, Bs[cur ^ 1], n0, (kt + 1) * GBK2, tid);
            cp_commit();
            cp_wait<1>();
        } else {
            cp_wait<0>();
        }
        __syncthreads();

#pragma unroll
        for (int ks = 0; ks < GBK2 / 16; ks++) {
            wmma::fragment<wmma::matrix_b, 16, 16, 16, __half, wmma::col_major> bf[2];
#pragma unroll
            for (int ni = 0; ni < 2; ni++)
                wmma::load_matrix_sync(
                    bf[ni], &Bs[cur][(wn * 32 + ni * 16) * GLDH + ks * 16], GLDH);
#pragma unroll
            for (int mi = 0; mi < 4; mi++) {
                wmma::fragment<wmma::matrix_a, 16, 16, 16, __half, wmma::row_major> af;
                wmma::load_matrix_sync(
                    af, &As[cur][(wm * 64 + mi * 16) * GLDH + ks * 16], GLDH);
#pragma unroll
                for (int ni = 0; ni < 2; ni++)
                    wmma::mma_sync(cf[mi][ni], af, bf[ni], cf[mi][ni]);
            }
        }

        if (kt + 1 < NKT)
            sta_f16(As[cur ^ 1], areg, tid);
        __syncthreads();
    }

    const int r = lane >> 1;
    const int c0 = (lane & 1) * 8;
#pragma unroll
    for (int mi = 0; mi < 4; mi++)
#pragma unroll
        for (int ni = 0; ni < 2; ni++) {
            wmma::store_matrix_sync(stg[warp], cf[mi][ni], SLD, wmma::mem_row_major);
            __syncwarp();
            const int nc = wn * 32 + ni * 16 + c0;
            __half2 h[4];
#pragma unroll
            for (int e = 0; e < 4; e++) {
                float v0 = stg[warp][r * SLD + c0 + e * 2]     + pbs[nc + e * 2];
                float v1 = stg[warp][r * SLD + c0 + e * 2 + 1] + pbs[nc + e * 2 + 1];
                h[e] = __floats2half2_rn(v0, v1);
            }
            *reinterpret_cast<uint4*>(
                &g_v16[(size_t)(m0 + wm * 64 + mi * 16 + r) * Dn + n0 + nc]) =
                *reinterpret_cast<uint4*>(h);
            __syncwarp();
        }
}

// ---------------------------------------------------------------------------
// Phase-1 (fp16 smem): unchanged (fully hidden under GEMM).
// ---------------------------------------------------------------------------
#define LT 64
#define RT (LT + 2 * PADn)  // 72

#define PB_QS    0
#define PB_DWS   9216
#define PB_PWW   18432
#define PB_AKW   27648
#define PB_PWOUT 29952
#define PB_WSM   47360
#define PB_DWW   52480
#define PB_PWB   53632
#define PB_AKB   53888
#define P_SMEM_BYTES 53952

__global__ __launch_bounds__(256) void sdconv_phase1(
    const float* __restrict__ q,
    const float* __restrict__ dw_w,
    const float* __restrict__ pw_w,
    const float* __restrict__ pw_b,
    const float* __restrict__ ak_w,
    const float* __restrict__ ak_b)
{
    extern __shared__ __align__(16) char smraw[];
    __half* qs    = (__half*)(smraw + PB_QS);
    __half* dws   = (__half*)(smraw + PB_DWS);
    __half* pww   = (__half*)(smraw + PB_PWW);
    __half* akw   = (__half*)(smraw + PB_AKW);
    float*  pwout = (float*)(smraw + PB_PWOUT);
    float*  wsm   = (float*)(smraw + PB_WSM);
    __half* dww   = (__half*)(smraw + PB_DWW);
    float*  pwbs  = (float*)(smraw + PB_PWB);
    float*  akbs  = (float*)(smraw + PB_AKB);

    const int tid = threadIdx.x;
    const int bb = blockIdx.z;
    const int h = blockIdx.y;
    const int l0 = blockIdx.x * LT;
    const int hbase = h * IPGn;

    for (int idx = tid; idx < RT * 64; idx += 256) {
        int r = idx >> 6, i = idx & 63;
        int gl = l0 - PADn + r;
        float v = (gl >= 0 && gl < Ln)
                      ? q[((size_t)(bb * Ln + gl)) * Dn + hbase + i] : 0.0f;
        qs[idx] = __float2half_rn(v);
    }
    for (int idx = tid; idx < 64 * 64; idx += 256) {
        int o = idx >> 6, i = idx & 63;
        pww[o * 72 + i] = __float2half_rn(pw_w[h * 4096 + idx]);
    }
    for (int idx = tid; idx < 16 * 64; idx += 256) {
        int kk = idx >> 6, i = idx & 63;
        akw[kk * 72 + i] = __float2half_rn(
            (kk < Kn) ? ak_w[h * 576 + kk * 64 + i] : 0.0f);
    }
    for (int idx = tid; idx < 64 * 9; idx += 256)
        dww[idx] = __float2half_rn(dw_w[hbase * 9 + idx]);
    if (tid < 64) pwbs[tid] = pw_b[hbase + tid];
    if (tid < 9)  akbs[tid] = ak_b[h * 9 + tid];
    __syncthreads();

    const int col = tid & 63;
    const int rq = tid >> 6;
    const int w = tid >> 5;

    {
        float wk[9];
#pragma unroll
        for (int k = 0; k < 9; k++) wk[k] = __half2float(dww[col * 9 + k]);
        float qr[24];
#pragma unroll
        for (int r = 0; r < 24; r++)
            qr[r] = __half2float(qs[(rq * 16 + r) * 64 + col]);
#pragma unroll
        for (int j = 0; j < 16; j++) {
            float s = 0.0f;
#pragma unroll
            for (int k = 0; k < 9; k++) s += qr[j + k] * wk[k];
            dws[(rq * 16 + j) * 72 + col] = __float2half_rn(s);
        }
    }
    __syncthreads();

    {
        const int tr = w >> 1;
        const int tc = (w & 1) * 2;
        wmma::fragment<wmma::accumulator, 16, 16, 16, float> c0, c1;
        wmma::fill_fragment(c0, 0.0f);
        wmma::fill_fragment(c1, 0.0f);
#pragma unroll
        for (int kk = 0; kk < 4; kk++) {
            wmma::fragment<wmma::matrix_a, 16, 16, 16, __half, wmma::row_major> a;
            wmma::fragment<wmma::matrix_b, 16, 16, 16, __half, wmma::col_major> b0, b1;
            wmma::load_matrix_sync(a, &dws[(tr * 16) * 72 + kk * 16], 72);
            wmma::load_matrix_sync(b0, &pww[(tc * 16) * 72 + kk * 16], 72);
            wmma::load_matrix_sync(b1, &pww[((tc + 1) * 16) * 72 + kk * 16], 72);
            wmma::mma_sync(c0, a, b0, c0);
            wmma::mma_sync(c1, a, b1, c1);
        }
        wmma::store_matrix_sync(&pwout[(tr * 16) * 68 + tc * 16], c0, 68,
                                wmma::mem_row_major);
        wmma::store_matrix_sync(&pwout[(tr * 16) * 68 + (tc + 1) * 16], c1, 68,
                                wmma::mem_row_major);
    }
    __syncthreads();

#pragma unroll
    for (int t = 0; t < 16; t++) {
        int idx = tid + t * 256;
        int l = idx >> 6, i = idx & 63;
        float ca = (pwout[l * 68 + i] + pwbs[i]) *
                   __half2float(qs[(l + PADn) * 64 + i]);
        dws[l * 72 + i] = __float2half_rn(ca);
    }
    __syncthreads();

    if (w < 4) {
        wmma::fragment<wmma::accumulator, 16, 16, 16, float> ck;
        wmma::fill_fragment(ck, 0.0f);
#pragma unroll
        for (int kk = 0; kk < 4; kk++) {
            wmma::fragment<wmma::matrix_a, 16, 16, 16, __half, wmma::row_major> a;
            wmma::fragment<wmma::matrix_b, 16, 16, 16, __half, wmma::col_major> b;
            wmma::load_matrix_sync(a, &dws[(w * 16) * 72 + kk * 16], 72);
            wmma::load_matrix_sync(b, &akw[kk * 16], 72);
            wmma::mma_sync(ck, a, b, ck);
        }
        wmma::store_matrix_sync(&wsm[(w * 16) * 20], ck, 20, wmma::mem_row_major);
    }
    __syncthreads();

    if (tid < LT) {
        int l = tid;
        float e[9], m = -1e30f;
#pragma unroll
        for (int k = 0; k < 9; k++) {
            e[k] = wsm[l * 20 + k] + akbs[k];
            m = fmaxf(m, e[k]);
        }
        float smx = 0.0f;
#pragma unroll
        for (int k = 0; k < 9; k++) { e[k] = expf(e[k] - m); smx += e[k]; }
        float inv = 1.0f / smx;
#pragma unroll
        for (int k = 0; k < 9; k++) wsm[l * 20 + k] = e[k] * inv;
    }
    __syncthreads();

    for (int t = tid; t < LT * 9; t += 256) {
        int l = t / 9, k = t - l * 9;
        g_w[((size_t)(bb * Ln + l0 + l) * Hn + h) * Kn + k] = wsm[l * 20 + k];
    }
}

// ---------------------------------------------------------------------------
// Phase-2: windowed gather over fp16 v, register stencil. b_base selects
// batch range so batches 0-2 can overlap the GEMM tail wave.
// ---------------------------------------------------------------------------
#define LT2 64
#define RT2 (LT2 + 2 * PADn)   // 72
#define G_OFF_VS 0
#define G_OFF_WS (G_OFF_VS + RT2 * 64)
#define G_FLOATS (G_OFF_WS + LT2 * 12)
#define G_SMEM_BYTES (G_FLOATS * 4)

__global__ __launch_bounds__(256) void sdconv_gather(
    float* __restrict__ out, int b_base)
{
    extern __shared__ __align__(16) float sm[];
    float* vs = sm + G_OFF_VS;
    float* ws = sm + G_OFF_WS;

    const int tid = threadIdx.x;
    const int bb = b_base + blockIdx.z;
    const int h = blockIdx.y;
    const int l0 = blockIdx.x * LT2;
    const int hbase = h * IPGn;

    for (int idx = tid; idx < RT2 * 8; idx += 256) {
        int r = idx >> 3, c8 = idx & 7;
        int gl = l0 - PADn + r;
        float4 f0, f1;
        if (gl >= 0 && gl < Ln) {
            uint4 raw = *reinterpret_cast<const uint4*>(
                &g_v16[((size_t)(bb * Ln + gl)) * Dn + hbase + c8 * 8]);
            const __half2* hp = reinterpret_cast<const __half2*>(&raw);
            float2 a = __half22float2(hp[0]), b = __half22float2(hp[1]);
            float2 c = __half22float2(hp[2]), d = __half22float2(hp[3]);
            f0 = make_float4(a.x, a.y, b.x, b.y);
            f1 = make_float4(c.x, c.y, d.x, d.y);
        } else {
            f0 = make_float4(0.f, 0.f, 0.f, 0.f);
            f1 = f0;
        }
        *reinterpret_cast<float4*>(&vs[r * 64 + c8 * 8]) = f0;
        *reinterpret_cast<float4*>(&vs[r * 64 + c8 * 8 + 4]) = f1;
    }
    for (int t = tid; t < LT2 * 9; t += 256) {
        int l = t / 9, k = t - l * 9;
        ws[l * 12 + k] = g_w[((size_t)(bb * Ln + l0 + l) * Hn + h) * Kn + k];
    }
    __syncthreads();

    const int col = tid & 63;
    const int rq = tid >> 6;

    float vr[24];
#pragma unroll
    for (int r = 0; r < 24; r++) vr[r] = vs[(rq * 16 + r) * 64 + col];
#pragma unroll
    for (int j = 0; j < 16; j++) {
        int l = rq * 16 + j;
        float4 w03 = *reinterpret_cast<const float4*>(&ws[l * 12]);
        float4 w47 = *reinterpret_cast<const float4*>(&ws[l * 12 + 4]);
        float w8 = ws[l * 12 + 8];
        float s = vr[j] * w03.x + vr[j + 1] * w03.y + vr[j + 2] * w03.z +
                  vr[j + 3] * w03.w + vr[j + 4] * w47.x + vr[j + 5] * w47.y +
                  vr[j + 6] * w47.z + vr[j + 7] * w47.w + vr[j + 8] * w8;
        out[((size_t)(bb * Ln + l0 + l)) * Dn + hbase + col] = s;
    }
}

// ---------------------------------------------------------------------------
extern "C" void kernel_launch(void* const* d_in, const int* in_sizes, int n_in,
                              void* d_out, int out_size)
{
    const float* query = (const float*)d_in[0];
    const float* dw_w  = (const float*)d_in[1];
    const float* pw_w  = (const float*)d_in[2];
    const float* pw_b  = (const float*)d_in[3];
    const float* ak_w  = (const float*)d_in[4];
    const float* ak_b  = (const float*)d_in[5];
    const float* pt_w  = (const float*)d_in[6];
    const float* pt_b  = (const float*)d_in[7];
    float* out = (float*)d_out;

    cudaFuncSetAttribute(sdconv_phase1,
                         cudaFuncAttributeMaxDynamicSharedMemorySize, P_SMEM_BYTES);

    __half* w16;  cudaGetSymbolAddress((void**)&w16, g_ptw16);

    cudaEventRecord(g_ss.e_fork, 0);
    cudaStreamWaitEvent(g_ss.s2, g_ss.e_fork, 0);

    const int nw4 = Dn * Dn / 4;
    cvt_fp16<<<(nw4 + 255) / 256, 256, 0, g_ss.s2>>>(
        (const float4*)pt_w, w16, nw4);

    // Asymmetric GEMM split: 288 CTAs (~1 full wave: batches 0-2), then
    // 96 CTAs (underfilled tail wave: batch 3).
    dim3 g1(Dn / GBN, 48);   // 6 x 48 = 288 CTAs, m-blocks 0..47
    dim3 g2(Dn / GBN, 16);   // 6 x 16 = 96 CTAs,  m-blocks 48..63
    gemm_h2<<<g1, 256, 0, g_ss.s2>>>(query, w16, pt_b, 0);
    cudaEventRecord(g_ss.e_half, g_ss.s2);
    gemm_h2<<<g2, 256, 0, g_ss.s2>>>(query, w16, pt_b, 48);
    cudaEventRecord(g_ss.e_join, g_ss.s2);

    // Phase-1 on main stream (concurrent with GEMM launch 1)
    dim3 pgrid(Ln / LT, Hn, Bn);                 // 32 x 12 x 4
    sdconv_phase1<<<pgrid, 256, P_SMEM_BYTES>>>(query, dw_w, pw_w, pw_b,
                                                ak_w, ak_b);

    // Gather batches 0-2 overlaps the GEMM tail wave (96 CTAs)
    cudaStreamWaitEvent(0, g_ss.e_half, 0);
    dim3 fga(Ln / LT2, Hn, 3);                   // 32 x 12 x 3
    sdconv_gather<<<fga, 256, G_SMEM_BYTES>>>(out, 0);

    // Gather batch 3 after full join
    cudaStreamWaitEvent(0, g_ss.e_join, 0);
    dim3 fgb(Ln / LT2, Hn, 1);                   // 32 x 12 x 1
    sdconv_gather<<<fgb, 256, G_SMEM_BYTES>>>(out, 3);
}

// round 16
// speedup vs baseline: 1.0300x; 1.0300x over previous
#include <cuda_runtime.h>
#include <cuda_fp16.h>
#include <mma.h>
#include <math.h>

using namespace nvcuda;

#define Bn 4
#define Ln 2048
#define Dn 768
#define Hn 12
#define Kn 9
#define IPGn 64
#define PADn 4

__device__ __half g_v16[Bn * Ln * Dn];     // 12.6 MB fp16 v (+bias folded)
__device__ float g_w[Bn * Ln * Hn * Kn];   // 3.5 MB softmax weights
__device__ __half g_ptw16[Dn * Dn];        // 1.2 MB fp16 pt_w

struct SideStream {
    cudaStream_t s2;
    cudaEvent_t e_fork, e_join;
    SideStream() {
        cudaStreamCreateWithFlags(&s2, cudaStreamNonBlocking);
        cudaEventCreateWithFlags(&e_fork, cudaEventDisableTiming);
        cudaEventCreateWithFlags(&e_join, cudaEventDisableTiming);
    }
};
static SideStream g_ss;

__device__ __forceinline__ void cp_async16(void* smem, const void* gmem) {
    unsigned s = (unsigned)__cvta_generic_to_shared(smem);
    asm volatile("cp.async.cg.shared.global [%0], [%1], 16;\n" :: "r"(s), "l"(gmem));
}
__device__ __forceinline__ void cp_commit() {
    asm volatile("cp.async.commit_group;\n" ::);
}
template <int N>
__device__ __forceinline__ void cp_wait() {
    asm volatile("cp.async.wait_group %0;\n" :: "n"(N));
}

// ---------------------------------------------------------------------------
// fp32 -> fp16 conversion (pt_w only; tiny)
// ---------------------------------------------------------------------------
__global__ __launch_bounds__(256) void cvt_fp16(
    const float4* __restrict__ in, __half* __restrict__ out, int n4)
{
    int idx = blockIdx.x * 256 + threadIdx.x;
    if (idx < n4) {
        float4 f = in[idx];
        *reinterpret_cast<__half2*>(out + (size_t)idx * 4) =
            __floats2half2_rn(f.x, f.y);
        *reinterpret_cast<__half2*>(out + (size_t)idx * 4 + 2) =
            __floats2half2_rn(f.z, f.w);
    }
}

// ---------------------------------------------------------------------------
// Kernel 1: v16 = half(query @ ptw16.T + pt_b)  (single full-grid launch)
// fp16 wmma m16n16k16, fp32 accum. Block 128x128, 8 warps (2m x 4n) of 64x32.
// ---------------------------------------------------------------------------
#define GBM 128
#define GBN 128
#define GBK2 32
#define GLDH 40
#define SLD 20   // staging ldm: multiple of 4 (wmma float frag requirement)

__device__ __forceinline__ void lda_f32(
    const float* __restrict__ A, float4* r, int m0, int k0, int tid)
{
#pragma unroll
    for (int v = 0; v < 4; v++) {
        int idx = tid + v * 256;
        int row = idx >> 3, c4 = idx & 7;
        r[v] = *reinterpret_cast<const float4*>(
            &A[(size_t)(m0 + row) * Dn + k0 + c4 * 4]);
    }
}
__device__ __forceinline__ void sta_f16(__half* As, const float4* r, int tid)
{
#pragma unroll
    for (int v = 0; v < 4; v++) {
        int idx = tid + v * 256;
        int row = idx >> 3, c4 = idx & 7;
        __half2* p = reinterpret_cast<__half2*>(&As[row * GLDH + c4 * 4]);
        p[0] = __floats2half2_rn(r[v].x, r[v].y);
        p[1] = __floats2half2_rn(r[v].z, r[v].w);
    }
}
__device__ __forceinline__ void ldb_cp(
    const __half* __restrict__ W, __half* Bs, int n0, int k0, int tid)
{
#pragma unroll
    for (int v = 0; v < 2; v++) {
        int idx = tid + v * 256;
        int r = idx >> 2, c = idx & 3;
        cp_async16(&Bs[r * GLDH + c * 8], &W[(size_t)(n0 + r) * Dn + k0 + c * 8]);
    }
}

__global__ __launch_bounds__(256) void gemm_h2(
    const float* __restrict__ A, const __half* __restrict__ W,
    const float* __restrict__ pt_b)
{
    __shared__ __align__(16) __half As[2][GBM * GLDH];
    __shared__ __align__(16) __half Bs[2][GBN * GLDH];
    __shared__ __align__(16) float stg[8][16 * SLD];
    __shared__ float pbs[GBN];

    const int tid = threadIdx.x;
    const int m0 = blockIdx.y * GBM;
    const int n0 = blockIdx.x * GBN;
    const int warp = tid >> 5;
    const int lane = tid & 31;
    const int wm = warp & 1;
    const int wn = warp >> 1;

    if (tid < GBN) pbs[tid] = pt_b[n0 + tid];

    wmma::fragment<wmma::accumulator, 16, 16, 16, float> cf[4][2];
#pragma unroll
    for (int mi = 0; mi < 4; mi++)
#pragma unroll
        for (int ni = 0; ni < 2; ni++)
            wmma::fill_fragment(cf[mi][ni], 0.0f);

    float4 areg[4];
    lda_f32(A, areg, m0, 0, tid);
    ldb_cp(W, Bs[0], n0, 0, tid);
    cp_commit();
    sta_f16(As[0], areg, tid);

    const int NKT = Dn / GBK2;  // 24
    for (int kt = 0; kt < NKT; kt++) {
        const int cur = kt & 1;
        if (kt + 1 < NKT) {
            lda_f32(A, areg, m0, (kt + 1) * GBK2, tid);
            ldb_cp(W, Bs[cur ^ 1], n0, (kt + 1) * GBK2, tid);
            cp_commit();
            cp_wait<1>();
        } else {
            cp_wait<0>();
        }
        __syncthreads();

#pragma unroll
        for (int ks = 0; ks < GBK2 / 16; ks++) {
            wmma::fragment<wmma::matrix_b, 16, 16, 16, __half, wmma::col_major> bf[2];
#pragma unroll
            for (int ni = 0; ni < 2; ni++)
                wmma::load_matrix_sync(
                    bf[ni], &Bs[cur][(wn * 32 + ni * 16) * GLDH + ks * 16], GLDH);
#pragma unroll
            for (int mi = 0; mi < 4; mi++) {
                wmma::fragment<wmma::matrix_a, 16, 16, 16, __half, wmma::row_major> af;
                wmma::load_matrix_sync(
                    af, &As[cur][(wm * 64 + mi * 16) * GLDH + ks * 16], GLDH);
#pragma unroll
                for (int ni = 0; ni < 2; ni++)
                    wmma::mma_sync(cf[mi][ni], af, bf[ni], cf[mi][ni]);
            }
        }

        if (kt + 1 < NKT)
            sta_f16(As[cur ^ 1], areg, tid);
        __syncthreads();
    }

    const int r = lane >> 1;
    const int c0 = (lane & 1) * 8;
#pragma unroll
    for (int mi = 0; mi < 4; mi++)
#pragma unroll
        for (int ni = 0; ni < 2; ni++) {
            wmma::store_matrix_sync(stg[warp], cf[mi][ni], SLD, wmma::mem_row_major);
            __syncwarp();
            const int nc = wn * 32 + ni * 16 + c0;
            __half2 h[4];
#pragma unroll
            for (int e = 0; e < 4; e++) {
                float v0 = stg[warp][r * SLD + c0 + e * 2]     + pbs[nc + e * 2];
                float v1 = stg[warp][r * SLD + c0 + e * 2 + 1] + pbs[nc + e * 2 + 1];
                h[e] = __floats2half2_rn(v0, v1);
            }
            *reinterpret_cast<uint4*>(
                &g_v16[(size_t)(m0 + wm * 64 + mi * 16 + r) * Dn + n0 + nc]) =
                *reinterpret_cast<uint4*>(h);
            __syncwarp();
        }
}

// ---------------------------------------------------------------------------
// Phase-1 (fp16 smem): unchanged (fully hidden under GEMM).
// ---------------------------------------------------------------------------
#define LT 64
#define RT (LT + 2 * PADn)  // 72

#define PB_QS    0
#define PB_DWS   9216
#define PB_PWW   18432
#define PB_AKW   27648
#define PB_PWOUT 29952
#define PB_WSM   47360
#define PB_DWW   52480
#define PB_PWB   53632
#define PB_AKB   53888
#define P_SMEM_BYTES 53952

__global__ __launch_bounds__(256) void sdconv_phase1(
    const float* __restrict__ q,
    const float* __restrict__ dw_w,
    const float* __restrict__ pw_w,
    const float* __restrict__ pw_b,
    const float* __restrict__ ak_w,
    const float* __restrict__ ak_b)
{
    extern __shared__ __align__(16) char smraw[];
    __half* qs    = (__half*)(smraw + PB_QS);
    __half* dws   = (__half*)(smraw + PB_DWS);
    __half* pww   = (__half*)(smraw + PB_PWW);
    __half* akw   = (__half*)(smraw + PB_AKW);
    float*  pwout = (float*)(smraw + PB_PWOUT);
    float*  wsm   = (float*)(smraw + PB_WSM);
    __half* dww   = (__half*)(smraw + PB_DWW);
    float*  pwbs  = (float*)(smraw + PB_PWB);
    float*  akbs  = (float*)(smraw + PB_AKB);

    const int tid = threadIdx.x;
    const int bb = blockIdx.z;
    const int h = blockIdx.y;
    const int l0 = blockIdx.x * LT;
    const int hbase = h * IPGn;

    for (int idx = tid; idx < RT * 64; idx += 256) {
        int r = idx >> 6, i = idx & 63;
        int gl = l0 - PADn + r;
        float v = (gl >= 0 && gl < Ln)
                      ? q[((size_t)(bb * Ln + gl)) * Dn + hbase + i] : 0.0f;
        qs[idx] = __float2half_rn(v);
    }
    for (int idx = tid; idx < 64 * 64; idx += 256) {
        int o = idx >> 6, i = idx & 63;
        pww[o * 72 + i] = __float2half_rn(pw_w[h * 4096 + idx]);
    }
    for (int idx = tid; idx < 16 * 64; idx += 256) {
        int kk = idx >> 6, i = idx & 63;
        akw[kk * 72 + i] = __float2half_rn(
            (kk < Kn) ? ak_w[h * 576 + kk * 64 + i] : 0.0f);
    }
    for (int idx = tid; idx < 64 * 9; idx += 256)
        dww[idx] = __float2half_rn(dw_w[hbase * 9 + idx]);
    if (tid < 64) pwbs[tid] = pw_b[hbase + tid];
    if (tid < 9)  akbs[tid] = ak_b[h * 9 + tid];
    __syncthreads();

    const int col = tid & 63;
    const int rq = tid >> 6;
    const int w = tid >> 5;

    {
        float wk[9];
#pragma unroll
        for (int k = 0; k < 9; k++) wk[k] = __half2float(dww[col * 9 + k]);
        float qr[24];
#pragma unroll
        for (int r = 0; r < 24; r++)
            qr[r] = __half2float(qs[(rq * 16 + r) * 64 + col]);
#pragma unroll
        for (int j = 0; j < 16; j++) {
            float s = 0.0f;
#pragma unroll
            for (int k = 0; k < 9; k++) s += qr[j + k] * wk[k];
            dws[(rq * 16 + j) * 72 + col] = __float2half_rn(s);
        }
    }
    __syncthreads();

    {
        const int tr = w >> 1;
        const int tc = (w & 1) * 2;
        wmma::fragment<wmma::accumulator, 16, 16, 16, float> c0, c1;
        wmma::fill_fragment(c0, 0.0f);
        wmma::fill_fragment(c1, 0.0f);
#pragma unroll
        for (int kk = 0; kk < 4; kk++) {
            wmma::fragment<wmma::matrix_a, 16, 16, 16, __half, wmma::row_major> a;
            wmma::fragment<wmma::matrix_b, 16, 16, 16, __half, wmma::col_major> b0, b1;
            wmma::load_matrix_sync(a, &dws[(tr * 16) * 72 + kk * 16], 72);
            wmma::load_matrix_sync(b0, &pww[(tc * 16) * 72 + kk * 16], 72);
            wmma::load_matrix_sync(b1, &pww[((tc + 1) * 16) * 72 + kk * 16], 72);
            wmma::mma_sync(c0, a, b0, c0);
            wmma::mma_sync(c1, a, b1, c1);
        }
        wmma::store_matrix_sync(&pwout[(tr * 16) * 68 + tc * 16], c0, 68,
                                wmma::mem_row_major);
        wmma::store_matrix_sync(&pwout[(tr * 16) * 68 + (tc + 1) * 16], c1, 68,
                                wmma::mem_row_major);
    }
    __syncthreads();

#pragma unroll
    for (int t = 0; t < 16; t++) {
        int idx = tid + t * 256;
        int l = idx >> 6, i = idx & 63;
        float ca = (pwout[l * 68 + i] + pwbs[i]) *
                   __half2float(qs[(l + PADn) * 64 + i]);
        dws[l * 72 + i] = __float2half_rn(ca);
    }
    __syncthreads();

    if (w < 4) {
        wmma::fragment<wmma::accumulator, 16, 16, 16, float> ck;
        wmma::fill_fragment(ck, 0.0f);
#pragma unroll
        for (int kk = 0; kk < 4; kk++) {
            wmma::fragment<wmma::matrix_a, 16, 16, 16, __half, wmma::row_major> a;
            wmma::fragment<wmma::matrix_b, 16, 16, 16, __half, wmma::col_major> b;
            wmma::load_matrix_sync(a, &dws[(w * 16) * 72 + kk * 16], 72);
            wmma::load_matrix_sync(b, &akw[kk * 16], 72);
            wmma::mma_sync(ck, a, b, ck);
        }
        wmma::store_matrix_sync(&wsm[(w * 16) * 20], ck, 20, wmma::mem_row_major);
    }
    __syncthreads();

    if (tid < LT) {
        int l = tid;
        float e[9], m = -1e30f;
#pragma unroll
        for (int k = 0; k < 9; k++) {
            e[k] = wsm[l * 20 + k] + akbs[k];
            m = fmaxf(m, e[k]);
        }
        float smx = 0.0f;
#pragma unroll
        for (int k = 0; k < 9; k++) { e[k] = expf(e[k] - m); smx += e[k]; }
        float inv = 1.0f / smx;
#pragma unroll
        for (int k = 0; k < 9; k++) wsm[l * 20 + k] = e[k] * inv;
    }
    __syncthreads();

    for (int t = tid; t < LT * 9; t += 256) {
        int l = t / 9, k = t - l * 9;
        g_w[((size_t)(bb * Ln + l0 + l) * Hn + h) * Kn + k] = wsm[l * 20 + k];
    }
}

// ---------------------------------------------------------------------------
// Phase-2: windowed gather over fp16 v. LT2=32, 128-thread CTAs (3072
// blocks) for latency hiding + smooth wave tail.
// ---------------------------------------------------------------------------
#define LT2 32
#define RT2 (LT2 + 2 * PADn)   // 40
#define G_OFF_VS 0                       // 40*64 floats = 2560
#define G_OFF_WS (G_OFF_VS + RT2 * 64)   // 32*12 = 384
#define G_FLOATS (G_OFF_WS + LT2 * 12)
#define G_SMEM_BYTES (G_FLOATS * 4)      // 11776

__global__ __launch_bounds__(128) void sdconv_gather(float* __restrict__ out)
{
    extern __shared__ __align__(16) float sm[];
    float* vs = sm + G_OFF_VS;
    float* ws = sm + G_OFF_WS;

    const int tid = threadIdx.x;
    const int bb = blockIdx.z;
    const int h = blockIdx.y;
    const int l0 = blockIdx.x * LT2;
    const int hbase = h * IPGn;

    // v tile: uint4 = 8 halves per load; convert to fp32 in smem
    for (int idx = tid; idx < RT2 * 8; idx += 128) {
        int r = idx >> 3, c8 = idx & 7;
        int gl = l0 - PADn + r;
        float4 f0, f1;
        if (gl >= 0 && gl < Ln) {
            uint4 raw = *reinterpret_cast<const uint4*>(
                &g_v16[((size_t)(bb * Ln + gl)) * Dn + hbase + c8 * 8]);
            const __half2* hp = reinterpret_cast<const __half2*>(&raw);
            float2 a = __half22float2(hp[0]), b = __half22float2(hp[1]);
            float2 c = __half22float2(hp[2]), d = __half22float2(hp[3]);
            f0 = make_float4(a.x, a.y, b.x, b.y);
            f1 = make_float4(c.x, c.y, d.x, d.y);
        } else {
            f0 = make_float4(0.f, 0.f, 0.f, 0.f);
            f1 = f0;
        }
        *reinterpret_cast<float4*>(&vs[r * 64 + c8 * 8]) = f0;
        *reinterpret_cast<float4*>(&vs[r * 64 + c8 * 8 + 4]) = f1;
    }
    for (int t = tid; t < LT2 * 9; t += 128) {
        int l = t / 9, k = t - l * 9;
        ws[l * 12 + k] = g_w[((size_t)(bb * Ln + l0 + l) * Hn + h) * Kn + k];
    }
    __syncthreads();

    const int col = tid & 63;
    const int rq = tid >> 6;   // 0..1, 16 positions each

    float vr[24];
#pragma unroll
    for (int r = 0; r < 24; r++) vr[r] = vs[(rq * 16 + r) * 64 + col];
#pragma unroll
    for (int j = 0; j < 16; j++) {
        int l = rq * 16 + j;
        float4 w03 = *reinterpret_cast<const float4*>(&ws[l * 12]);
        float4 w47 = *reinterpret_cast<const float4*>(&ws[l * 12 + 4]);
        float w8 = ws[l * 12 + 8];
        float s = vr[j] * w03.x + vr[j + 1] * w03.y + vr[j + 2] * w03.z +
                  vr[j + 3] * w03.w + vr[j + 4] * w47.x + vr[j + 5] * w47.y +
                  vr[j + 6] * w47.z + vr[j + 7] * w47.w + vr[j + 8] * w8;
        out[((size_t)(bb * Ln + l0 + l)) * Dn + hbase + col] = s;
    }
}

// ---------------------------------------------------------------------------
extern "C" void kernel_launch(void* const* d_in, const int* in_sizes, int n_in,
                              void* d_out, int out_size)
{
    const float* query = (const float*)d_in[0];
    const float* dw_w  = (const float*)d_in[1];
    const float* pw_w  = (const float*)d_in[2];
    const float* pw_b  = (const float*)d_in[3];
    const float* ak_w  = (const float*)d_in[4];
    const float* ak_b  = (const float*)d_in[5];
    const float* pt_w  = (const float*)d_in[6];
    const float* pt_b  = (const float*)d_in[7];
    float* out = (float*)d_out;

    cudaFuncSetAttribute(sdconv_phase1,
                         cudaFuncAttributeMaxDynamicSharedMemorySize, P_SMEM_BYTES);

    __half* w16;  cudaGetSymbolAddress((void**)&w16, g_ptw16);

    cudaEventRecord(g_ss.e_fork, 0);
    cudaStreamWaitEvent(g_ss.s2, g_ss.e_fork, 0);

    const int nw4 = Dn * Dn / 4;
    cvt_fp16<<<(nw4 + 255) / 256, 256, 0, g_ss.s2>>>(
        (const float4*)pt_w, w16, nw4);

    dim3 ggrid(Dn / GBN, (Bn * Ln) / GBM);     // 6 x 64 (single launch)
    gemm_h2<<<ggrid, 256, 0, g_ss.s2>>>(query, w16, pt_b);

    dim3 pgrid(Ln / LT, Hn, Bn);               // 32 x 12 x 4
    sdconv_phase1<<<pgrid, 256, P_SMEM_BYTES>>>(query, dw_w, pw_w, pw_b,
                                                ak_w, ak_b);

    cudaEventRecord(g_ss.e_join, g_ss.s2);
    cudaStreamWaitEvent(0, g_ss.e_join, 0);

    dim3 fgrid(Ln / LT2, Hn, Bn);              // 64 x 12 x 4 = 3072
    sdconv_gather<<<fgrid, 128, G_SMEM_BYTES>>>(out);
}